// round 1
// baseline (speedup 1.0000x reference)
#include <cuda_runtime.h>
#include <cuda_bf16.h>
#include <mma.h>
#include <math.h>
#include <stdint.h>

using namespace nvcuda;

#define TOKENS_MAX 4096
#define D_DIM 1024
#define V_DIM 50257

#define BM 64
#define BN 64
#define BK 32
#define KSTEPS (D_DIM / BK)

// ---------------- scratch (device globals: allocation-free rule) ----------------
__device__ __nv_bfloat16 g_Wb[(size_t)V_DIM * D_DIM];     // bf16 W
__device__ __nv_bfloat16 g_Ab[(size_t)TOKENS_MAX * D_DIM]; // gathered bf16 activations
__device__ int   g_valid_idx[TOKENS_MAX];
__device__ int   g_tgt[TOKENS_MAX];
__device__ int   g_nvalid;
__device__ float g_sumexp[TOKENS_MAX];
__device__ float g_sumlogit[TOKENS_MAX];
__device__ float g_tlogit[TOKENS_MAX];

// ---------------- fast exp on FMA/ALU pipes (avoid MUFU bottleneck) ----------------
__device__ __forceinline__ float fast_expf(float x) {
    // exp(x) = 2^t, t = x*log2(e) = k + f, f in [0,1)
    float t = x * 1.4426950408889634f;
    float k = floorf(t);
    float f = t - k;
    // degree-6 Taylor of 2^f (rel err ~8e-6 on [0,1))
    float p = 1.5403530393381608e-4f;
    p = fmaf(p, f, 1.3333558146428443e-3f);
    p = fmaf(p, f, 9.6181291076284771e-3f);
    p = fmaf(p, f, 5.5504108664821579e-2f);
    p = fmaf(p, f, 2.4022650695910071e-1f);
    p = fmaf(p, f, 6.9314718055994531e-1f);
    p = fmaf(p, f, 1.0f);
    int ki = (int)k;
    float s = __int_as_float((ki + 127) << 23);
    return p * s;
}

// ---------------- kernel 1: mask-dtype detect + compact valid tokens ----------------
__global__ void gather_kernel(const int* __restrict__ targets,
                              const unsigned char* __restrict__ masks_raw,
                              int n_tokens) {
    __shared__ int s_isu8;
    __shared__ int wsum[32];
    int tid = threadIdx.x;
    if (tid == 0) s_isu8 = 0;
    __syncthreads();

    // Detect whether masks are 1-byte bool or int32: int32 0/1 values have
    // zero bytes at every offset i%4 != 0 within the first n_tokens bytes.
    int flag = 0;
    for (int i = tid; i < n_tokens; i += blockDim.x)
        if ((i & 3) != 0 && masks_raw[i] != 0) flag = 1;
    if (flag) atomicOr(&s_isu8, 1);
    __syncthreads();
    const bool isu8 = (s_isu8 != 0);
    const int* masks_i32 = (const int*)masks_raw;

    // per-thread contiguous chunk
    int C = (n_tokens + blockDim.x - 1) / blockDim.x;
    int start = tid * C;
    int end = min(start + C, n_tokens);
    int cnt = 0;
    for (int i = start; i < end; i++)
        cnt += isu8 ? (masks_raw[i] != 0) : (masks_i32[i] != 0);

    // block exclusive scan
    int lane = tid & 31, wid = tid >> 5;
    int v = cnt;
    #pragma unroll
    for (int o = 1; o < 32; o <<= 1) {
        int t = __shfl_up_sync(0xffffffffu, v, o);
        if (lane >= o) v += t;
    }
    if (lane == 31) wsum[wid] = v;
    __syncthreads();
    if (wid == 0) {
        int nw = blockDim.x >> 5;
        int w = (lane < nw) ? wsum[lane] : 0;
        #pragma unroll
        for (int o = 1; o < 32; o <<= 1) {
            int t = __shfl_up_sync(0xffffffffu, w, o);
            if (lane >= o) w += t;
        }
        wsum[lane] = w;
    }
    __syncthreads();
    int excl = v - cnt + (wid > 0 ? wsum[wid - 1] : 0);

    int off = excl;
    for (int i = start; i < end; i++) {
        bool mk = isu8 ? (masks_raw[i] != 0) : (masks_i32[i] != 0);
        if (mk) {
            g_valid_idx[off] = i;
            g_tgt[off] = targets[i];
            off++;
        }
    }
    if (tid == blockDim.x - 1) g_nvalid = excl + cnt; // global total
}

// ---------------- kernel 2: gather + convert activations to bf16, zero partials ----------------
__global__ void build_a_kernel(const float* __restrict__ outputs) {
    int m = blockIdx.x;
    int tid = threadIdx.x;
    if (tid == 0) {
        g_sumexp[m] = 0.f;
        g_sumlogit[m] = 0.f;
        g_tlogit[m] = 0.f;
    }
    int nv = g_nvalid;
    __nv_bfloat16* dst = g_Ab + (size_t)m * D_DIM;
    if (m < nv) {
        const float* src = outputs + (size_t)g_valid_idx[m] * D_DIM;
        for (int i = tid * 4; i < D_DIM; i += blockDim.x * 4) {
            float4 v = *(const float4*)(src + i);
            *(__nv_bfloat162*)(dst + i)     = __floats2bfloat162_rn(v.x, v.y);
            *(__nv_bfloat162*)(dst + i + 2) = __floats2bfloat162_rn(v.z, v.w);
        }
    } else {
        __nv_bfloat162 z = __floats2bfloat162_rn(0.f, 0.f);
        for (int i = tid * 4; i < D_DIM; i += blockDim.x * 4) {
            *(__nv_bfloat162*)(dst + i)     = z;
            *(__nv_bfloat162*)(dst + i + 2) = z;
        }
    }
}

// ---------------- kernel 3: W fp32 -> bf16 ----------------
__global__ void conv_w_kernel(const float* __restrict__ W, long n) {
    long i = ((long)blockIdx.x * blockDim.x + threadIdx.x) * 4;
    if (i < n) {
        float4 v = *(const float4*)(W + i);
        *(__nv_bfloat162*)(g_Wb + i)     = __floats2bfloat162_rn(v.x, v.y);
        *(__nv_bfloat162*)(g_Wb + i + 2) = __floats2bfloat162_rn(v.z, v.w);
    }
}

// ---------------- kernel 4: fused GEMM + per-tile softmax-stat epilogue ----------------
__device__ __forceinline__ void load_tiles(__nv_bfloat16 (*As)[BK + 8],
                                           __nv_bfloat16 (*Bs)[BK + 8],
                                           int m0, int n0, int k0, int tid) {
    #pragma unroll
    for (int rep = 0; rep < 2; rep++) {
        int chunk = tid + rep * 128;       // 256 chunks of 8 bf16 each
        int row = chunk >> 2;
        int col = (chunk & 3) << 3;
        // A (rows are zero-padded beyond n_valid, always in-bounds)
        const uint4* asrc = (const uint4*)(g_Ab + (size_t)(m0 + row) * D_DIM + k0 + col);
        *(uint4*)&As[row][col] = *asrc;
        // B (W rows beyond V zero-filled; epilogue excludes those columns)
        int vr = n0 + row;
        uint4 bv = make_uint4(0u, 0u, 0u, 0u);
        if (vr < V_DIM)
            bv = *(const uint4*)(g_Wb + (size_t)vr * D_DIM + k0 + col);
        *(uint4*)&Bs[row][col] = bv;
    }
}

__global__ void __launch_bounds__(128) gemm_epilogue_kernel() {
    __shared__ alignas(16) __nv_bfloat16 As[2][BM][BK + 8];
    __shared__ alignas(16) __nv_bfloat16 Bs[2][BN][BK + 8];
    __shared__ alignas(16) float Cs[BM][BN + 4];

    int nv = g_nvalid;
    int m0 = blockIdx.x * BM;       // x = token tile (fast) -> W tile reuse in L2
    if (m0 >= nv) return;
    int n0 = blockIdx.y * BN;

    int tid = threadIdx.x;
    int warp = tid >> 5;
    int wm = warp >> 1, wn = warp & 1;   // 2x2 warps, each 32x32

    wmma::fragment<wmma::accumulator, 16, 16, 16, float> acc[2][2];
    #pragma unroll
    for (int i = 0; i < 2; i++)
        #pragma unroll
        for (int j = 0; j < 2; j++)
            wmma::fill_fragment(acc[i][j], 0.0f);

    load_tiles(As[0], Bs[0], m0, n0, 0, tid);
    __syncthreads();

    for (int ks = 0; ks < KSTEPS; ks++) {
        int cur = ks & 1;
        if (ks + 1 < KSTEPS)
            load_tiles(As[cur ^ 1], Bs[cur ^ 1], m0, n0, (ks + 1) * BK, tid);

        #pragma unroll
        for (int kk = 0; kk < BK; kk += 16) {
            wmma::fragment<wmma::matrix_a, 16, 16, 16, __nv_bfloat16, wmma::row_major> a0, a1;
            wmma::fragment<wmma::matrix_b, 16, 16, 16, __nv_bfloat16, wmma::col_major> b0, b1;
            wmma::load_matrix_sync(a0, &As[cur][wm * 32 + 0][kk], BK + 8);
            wmma::load_matrix_sync(a1, &As[cur][wm * 32 + 16][kk], BK + 8);
            wmma::load_matrix_sync(b0, &Bs[cur][wn * 32 + 0][kk], BK + 8);
            wmma::load_matrix_sync(b1, &Bs[cur][wn * 32 + 16][kk], BK + 8);
            wmma::mma_sync(acc[0][0], a0, b0, acc[0][0]);
            wmma::mma_sync(acc[0][1], a0, b1, acc[0][1]);
            wmma::mma_sync(acc[1][0], a1, b0, acc[1][0]);
            wmma::mma_sync(acc[1][1], a1, b1, acc[1][1]);
        }
        __syncthreads();
    }

    // stage logits tile to smem
    #pragma unroll
    for (int i = 0; i < 2; i++)
        #pragma unroll
        for (int j = 0; j < 2; j++)
            wmma::store_matrix_sync(&Cs[wm * 32 + i * 16][wn * 32 + j * 16],
                                    acc[i][j], BN + 4, wmma::mem_row_major);
    __syncthreads();

    // per-row reduce: sum exp(logit), sum logit; capture target logit
    int row = tid >> 1;
    int half = tid & 1;
    int gm = m0 + row;
    float se = 0.f, sl = 0.f;
    int cbase = half * 32;
    #pragma unroll 8
    for (int c = 0; c < 32; c++) {
        int n = n0 + cbase + c;
        if (n < V_DIM) {
            float v = Cs[row][cbase + c];
            se += fast_expf(v);
            sl += v;
        }
    }
    se += __shfl_xor_sync(0xffffffffu, se, 1);
    sl += __shfl_xor_sync(0xffffffffu, sl, 1);
    if (half == 0 && gm < nv) {
        atomicAdd(&g_sumexp[gm], se);
        atomicAdd(&g_sumlogit[gm], sl);
        int t = g_tgt[gm];
        if (t >= n0 && t < n0 + BN)
            g_tlogit[gm] = Cs[row][t - n0];
    }
}

// ---------------- kernel 5: final scalar reduction ----------------
__global__ void final_kernel(float* __restrict__ out) {
    __shared__ double s_n[32], s_s[32];
    int tid = threadIdx.x;
    int nv = g_nvalid;
    double nll = 0.0, slp = 0.0;
    for (int m = tid; m < nv; m += blockDim.x) {
        float lse = logf(g_sumexp[m]);
        nll += (double)lse - (double)g_tlogit[m];
        slp += (double)g_sumlogit[m] - (double)V_DIM * (double)lse;
    }
    #pragma unroll
    for (int o = 16; o; o >>= 1) {
        nll += __shfl_down_sync(0xffffffffu, nll, o);
        slp += __shfl_down_sync(0xffffffffu, slp, o);
    }
    if ((tid & 31) == 0) { s_n[tid >> 5] = nll; s_s[tid >> 5] = slp; }
    __syncthreads();
    if (tid < 32) {
        int nw = blockDim.x >> 5;
        nll = (tid < nw) ? s_n[tid] : 0.0;
        slp = (tid < nw) ? s_s[tid] : 0.0;
        #pragma unroll
        for (int o = 16; o; o >>= 1) {
            nll += __shfl_down_sync(0xffffffffu, nll, o);
            slp += __shfl_down_sync(0xffffffffu, slp, o);
        }
        if (tid == 0) {
            double n = (double)nv;
            double loss = 0.9 * (nll / n) - 0.1 * (slp / (n * (double)V_DIM));
            out[0] = (float)loss;
        }
    }
}

// ---------------- launch ----------------
extern "C" void kernel_launch(void* const* d_in, const int* in_sizes, int n_in,
                              void* d_out, int out_size) {
    const int*           targets = (const int*)d_in[0];
    const unsigned char* masks   = (const unsigned char*)d_in[1];
    const float*         outputs = (const float*)d_in[2];
    const float*         W       = (const float*)d_in[3];
    int n_tokens = in_sizes[0];   // 4096

    gather_kernel<<<1, 1024>>>(targets, masks, n_tokens);
    build_a_kernel<<<n_tokens, 256>>>(outputs);

    long nw = (long)V_DIM * D_DIM;
    int conv_blocks = (int)((nw / 4 + 255) / 256);
    conv_w_kernel<<<conv_blocks, 256>>>(W, nw);

    dim3 grid((n_tokens + BM - 1) / BM, (V_DIM + BN - 1) / BN);
    gemm_epilogue_kernel<<<grid, 128>>>();

    final_kernel<<<1, 1024>>>((float*)d_out);
}

// round 3
// speedup vs baseline: 1.2340x; 1.2340x over previous
#include <cuda_runtime.h>
#include <cuda_bf16.h>
#include <mma.h>
#include <math.h>
#include <stdint.h>

using namespace nvcuda;

#define TOKENS_MAX 4096
#define D_DIM 1024
#define V_DIM 50257
#define BM 128
#define BN 256
#define BK 32
#define N_TILES 197                        // ceil(50257/256)
#define V_PAD (N_TILES * BN)               // 50432
#define KSTEPS (D_DIM / BK)                // 32
#define STAGES 3

#define LDS_PAD 40                          // smem row stride in elements (80B, bank-clean)
#define A_STAGE_BYTES (BM * LDS_PAD * 2)    // 10240
#define B_STAGE_BYTES (BN * LDS_PAD * 2)    // 20480
#define STAGE_BYTES (A_STAGE_BYTES + B_STAGE_BYTES)  // 30720
#define CS_LD (BN + 8)                      // 264 floats
#define SMEM_TOTAL (BM * CS_LD * 4)         // 135168 > 3*STAGE_BYTES (92160)

// ---------------- device-global scratch (allocation-free rule) ----------------
__device__ __align__(128) __nv_bfloat16 g_Wb[(size_t)V_PAD * D_DIM];
__device__ __align__(128) __nv_bfloat16 g_Ab[(size_t)TOKENS_MAX * D_DIM];
__device__ int   g_valid_idx[TOKENS_MAX];
__device__ int   g_tgt[TOKENS_MAX];
__device__ int   g_nvalid;
__device__ float g_sumexp[TOKENS_MAX];
__device__ float g_sumlogit[TOKENS_MAX];
__device__ float g_tlogit[TOKENS_MAX];

__device__ __forceinline__ uint32_t smem_u32(const void* p) {
    uint32_t a;
    asm("{ .reg .u64 t; cvta.to.shared.u64 t, %1; cvt.u32.u64 %0, t; }" : "=r"(a) : "l"(p));
    return a;
}
__device__ __forceinline__ void cp16(uint32_t dst, const void* src) {
    asm volatile("cp.async.cg.shared.global [%0], [%1], 16;\n" :: "r"(dst), "l"(src));
}

// ---------------- kernel 1: mask-dtype detect + compact valid tokens ----------------
__global__ void gather_kernel(const int* __restrict__ targets,
                              const unsigned char* __restrict__ masks_raw,
                              int n_tokens) {
    __shared__ int s_isu8;
    __shared__ int wsum[32];
    int tid = threadIdx.x;
    if (tid == 0) s_isu8 = 0;
    __syncthreads();

    // int32 0/1 values have zero bytes at offsets i%4!=0 in the first n bytes
    int flag = 0;
    for (int i = tid; i < n_tokens; i += blockDim.x)
        if ((i & 3) != 0 && masks_raw[i] != 0) flag = 1;
    if (flag) atomicOr(&s_isu8, 1);
    __syncthreads();
    const bool isu8 = (s_isu8 != 0);
    const int* masks_i32 = (const int*)masks_raw;

    int C = (n_tokens + blockDim.x - 1) / blockDim.x;
    int start = tid * C;
    int end = min(start + C, n_tokens);
    int cnt = 0;
    for (int i = start; i < end; i++)
        cnt += isu8 ? (masks_raw[i] != 0) : (masks_i32[i] != 0);

    int lane = tid & 31, wid = tid >> 5;
    int v = cnt;
    #pragma unroll
    for (int o = 1; o < 32; o <<= 1) {
        int t = __shfl_up_sync(0xffffffffu, v, o);
        if (lane >= o) v += t;
    }
    if (lane == 31) wsum[wid] = v;
    __syncthreads();
    if (wid == 0) {
        int nw = blockDim.x >> 5;
        int w = (lane < nw) ? wsum[lane] : 0;
        #pragma unroll
        for (int o = 1; o < 32; o <<= 1) {
            int t = __shfl_up_sync(0xffffffffu, w, o);
            if (lane >= o) w += t;
        }
        wsum[lane] = w;
    }
    __syncthreads();
    int excl = v - cnt + (wid > 0 ? wsum[wid - 1] : 0);

    int off = excl;
    for (int i = start; i < end; i++) {
        bool mk = isu8 ? (masks_raw[i] != 0) : (masks_i32[i] != 0);
        if (mk) {
            g_valid_idx[off] = i;
            g_tgt[off] = targets[i];
            off++;
        }
    }
    if (tid == blockDim.x - 1) g_nvalid = excl + cnt;
}

// ---------------- kernel 2: gather + convert activations to bf16, zero partials ----------------
__global__ void build_a_kernel(const float* __restrict__ outputs) {
    int m = blockIdx.x;
    int tid = threadIdx.x;
    if (tid == 0) {
        g_sumexp[m] = 0.f;
        g_sumlogit[m] = 0.f;
        g_tlogit[m] = 0.f;
    }
    int nv = g_nvalid;
    __nv_bfloat16* dst = g_Ab + (size_t)m * D_DIM;
    if (m < nv) {
        const float* src = outputs + (size_t)g_valid_idx[m] * D_DIM;
        for (int i = tid * 4; i < D_DIM; i += blockDim.x * 4) {
            float4 v = *(const float4*)(src + i);
            *(__nv_bfloat162*)(dst + i)     = __floats2bfloat162_rn(v.x, v.y);
            *(__nv_bfloat162*)(dst + i + 2) = __floats2bfloat162_rn(v.z, v.w);
        }
    } else {
        __nv_bfloat162 z = __floats2bfloat162_rn(0.f, 0.f);
        for (int i = tid * 4; i < D_DIM; i += blockDim.x * 4) {
            *(__nv_bfloat162*)(dst + i)     = z;
            *(__nv_bfloat162*)(dst + i + 2) = z;
        }
    }
}

// ---------------- kernel 3: W fp32 -> bf16 (zero-pad rows V_DIM..V_PAD) ----------------
__global__ void conv_w_kernel(const float* __restrict__ W) {
    long i = ((long)blockIdx.x * blockDim.x + threadIdx.x) * 4;
    const long nreal = (long)V_DIM * D_DIM;
    const long ntot  = (long)V_PAD * D_DIM;
    if (i < ntot) {
        if (i < nreal) {
            float4 v = *(const float4*)(W + i);
            *(__nv_bfloat162*)(g_Wb + i)     = __floats2bfloat162_rn(v.x, v.y);
            *(__nv_bfloat162*)(g_Wb + i + 2) = __floats2bfloat162_rn(v.z, v.w);
        } else {
            __nv_bfloat162 z = __floats2bfloat162_rn(0.f, 0.f);
            *(__nv_bfloat162*)(g_Wb + i)     = z;
            *(__nv_bfloat162*)(g_Wb + i + 2) = z;
        }
    }
}

// ---------------- kernel 4: 128x256x32 HMMA GEMM + softmax-stat epilogue ----------------
__global__ void __launch_bounds__(256, 1) gemm_epilogue_kernel() {
    extern __shared__ char smem[];
    uint32_t sb = smem_u32(smem);

    int nv = g_nvalid;
    int m0 = blockIdx.x * BM;
    if (m0 >= nv) return;
    int n0 = blockIdx.y * BN;

    int tid = threadIdx.x;
    int warp = tid >> 5, lane = tid & 31;
    int wm = warp & 1;        // 2 M-warps (rows wm*64..+63)
    int wn = warp >> 1;       // 4 N-warps (cols wn*64..+63)

    // per-thread cp.async slots: A 2 x 16B-chunks, B 4 x 16B-chunks per stage
    uint32_t adst[2], bdst[4];
    size_t   asrc[2], bsrc[4];
    const char* Ag = (const char*)g_Ab;
    const char* Wg = (const char*)g_Wb;
    #pragma unroll
    for (int i = 0; i < 2; i++) {
        int c = tid + i * 256;             // 512 chunks = 128 rows x 4
        int row = c >> 2, cc = (c & 3) << 4;
        adst[i] = (uint32_t)(row * (LDS_PAD * 2) + cc);
        asrc[i] = (size_t)(m0 + row) * 2048 + cc;
    }
    #pragma unroll
    for (int i = 0; i < 4; i++) {
        int c = tid + i * 256;             // 1024 chunks = 256 rows x 4
        int row = c >> 2, cc = (c & 3) << 4;
        bdst[i] = (uint32_t)(row * (LDS_PAD * 2) + cc);
        bsrc[i] = (size_t)(n0 + row) * 2048 + cc;
    }

    wmma::fragment<wmma::accumulator, 16, 16, 16, float> acc[4][4];
    #pragma unroll
    for (int i = 0; i < 4; i++)
        #pragma unroll
        for (int j = 0; j < 4; j++)
            wmma::fill_fragment(acc[i][j], 0.0f);

    // prologue: 2 stages in flight
    #pragma unroll
    for (int s = 0; s < 2; s++) {
        uint32_t ab = sb + s * STAGE_BYTES;
        uint32_t bb = ab + A_STAGE_BYTES;
        size_t kb = (size_t)s * (BK * 2);
        #pragma unroll
        for (int i = 0; i < 2; i++) cp16(ab + adst[i], Ag + asrc[i] + kb);
        #pragma unroll
        for (int i = 0; i < 4; i++) cp16(bb + bdst[i], Wg + bsrc[i] + kb);
        asm volatile("cp.async.commit_group;" ::: "memory");
    }

    for (int j = 0; j < KSTEPS; j++) {
        asm volatile("cp.async.wait_group 1;" ::: "memory");
        __syncthreads();

        // prefetch stage j+2 (empty commit keeps group accounting uniform)
        if (j + 2 < KSTEPS) {
            int s = (j + 2) % STAGES;
            uint32_t ab = sb + s * STAGE_BYTES;
            uint32_t bb = ab + A_STAGE_BYTES;
            size_t kb = (size_t)(j + 2) * (BK * 2);
            #pragma unroll
            for (int i = 0; i < 2; i++) cp16(ab + adst[i], Ag + asrc[i] + kb);
            #pragma unroll
            for (int i = 0; i < 4; i++) cp16(bb + bdst[i], Wg + bsrc[i] + kb);
        }
        asm volatile("cp.async.commit_group;" ::: "memory");

        // compute stage j
        int s = j % STAGES;
        const __nv_bfloat16* As = (const __nv_bfloat16*)(smem + s * STAGE_BYTES);
        const __nv_bfloat16* Bs = (const __nv_bfloat16*)(smem + s * STAGE_BYTES + A_STAGE_BYTES);
        #pragma unroll
        for (int kk = 0; kk < BK; kk += 16) {
            wmma::fragment<wmma::matrix_a, 16, 16, 16, __nv_bfloat16, wmma::row_major> a[4];
            wmma::fragment<wmma::matrix_b, 16, 16, 16, __nv_bfloat16, wmma::col_major> b[4];
            #pragma unroll
            for (int i = 0; i < 4; i++)
                wmma::load_matrix_sync(a[i], As + (wm * 64 + i * 16) * LDS_PAD + kk, LDS_PAD);
            #pragma unroll
            for (int jj = 0; jj < 4; jj++)
                wmma::load_matrix_sync(b[jj], Bs + (wn * 64 + jj * 16) * LDS_PAD + kk, LDS_PAD);
            #pragma unroll
            for (int i = 0; i < 4; i++)
                #pragma unroll
                for (int jj = 0; jj < 4; jj++)
                    wmma::mma_sync(acc[i][jj], a[i], b[jj], acc[i][jj]);
        }
        __syncthreads();
    }

    // ---- epilogue: stage full C tile (fp32) in smem, reduce per row ----
    float* Cs = (float*)smem;
    #pragma unroll
    for (int i = 0; i < 4; i++)
        #pragma unroll
        for (int jj = 0; jj < 4; jj++)
            wmma::store_matrix_sync(Cs + (wm * 64 + i * 16) * CS_LD + wn * 64 + jj * 16,
                                    acc[i][jj], CS_LD, wmma::mem_row_major);
    __syncthreads();

    int row = tid >> 1;            // 128 rows, 2 threads each
    int half = tid & 1;
    int gm = m0 + row;
    const float* crow = Cs + row * CS_LD + half * 128;
    int c0 = n0 + half * 128;
    float se = 0.f, sl = 0.f;
    #pragma unroll 4
    for (int c = 0; c < 128; c++) {
        int col = c0 + c;
        if (col < V_DIM) {
            float v = crow[c];
            se += __expf(v);
            sl += v;
        }
    }
    se += __shfl_xor_sync(0xffffffffu, se, 1);
    sl += __shfl_xor_sync(0xffffffffu, sl, 1);
    if (half == 0 && gm < nv) {
        atomicAdd(&g_sumexp[gm], se);
        atomicAdd(&g_sumlogit[gm], sl);
        int t = g_tgt[gm];
        if (t >= n0 && t < n0 + BN)
            g_tlogit[gm] = Cs[row * CS_LD + (t - n0)];
    }
}

// ---------------- kernel 5: final scalar reduction ----------------
__global__ void final_kernel(float* __restrict__ out) {
    __shared__ double s_n[32], s_s[32];
    int tid = threadIdx.x;
    int nv = g_nvalid;
    double nll = 0.0, slp = 0.0;
    for (int m = tid; m < nv; m += blockDim.x) {
        float lse = logf(g_sumexp[m]);
        nll += (double)lse - (double)g_tlogit[m];
        slp += (double)g_sumlogit[m] - (double)V_DIM * (double)lse;
    }
    #pragma unroll
    for (int o = 16; o; o >>= 1) {
        nll += __shfl_down_sync(0xffffffffu, nll, o);
        slp += __shfl_down_sync(0xffffffffu, slp, o);
    }
    if ((tid & 31) == 0) { s_n[tid >> 5] = nll; s_s[tid >> 5] = slp; }
    __syncthreads();
    if (tid < 32) {
        int nw = blockDim.x >> 5;
        nll = (tid < nw) ? s_n[tid] : 0.0;
        slp = (tid < nw) ? s_s[tid] : 0.0;
        #pragma unroll
        for (int o = 16; o; o >>= 1) {
            nll += __shfl_down_sync(0xffffffffu, nll, o);
            slp += __shfl_down_sync(0xffffffffu, slp, o);
        }
        if (tid == 0) {
            double n = (double)nv;
            double loss = 0.9 * (nll / n) - 0.1 * (slp / (n * (double)V_DIM));
            out[0] = (float)loss;
        }
    }
}

// ---------------- launch ----------------
extern "C" void kernel_launch(void* const* d_in, const int* in_sizes, int n_in,
                              void* d_out, int out_size) {
    const int*           targets = (const int*)d_in[0];
    const unsigned char* masks   = (const unsigned char*)d_in[1];
    const float*         outputs = (const float*)d_in[2];
    const float*         W       = (const float*)d_in[3];
    int n_tokens = in_sizes[0];   // 4096

    static int s_attr_done = 0;
    if (!s_attr_done) {
        cudaFuncSetAttribute(gemm_epilogue_kernel,
                             cudaFuncAttributeMaxDynamicSharedMemorySize, SMEM_TOTAL);
        s_attr_done = 1;
    }

    gather_kernel<<<1, 1024>>>(targets, masks, n_tokens);
    build_a_kernel<<<n_tokens, 256>>>(outputs);

    long ntot = (long)V_PAD * D_DIM;
    int conv_blocks = (int)((ntot / 4 + 255) / 256);
    conv_w_kernel<<<conv_blocks, 256>>>(W);

    dim3 grid((TOKENS_MAX + BM - 1) / BM, N_TILES);
    gemm_epilogue_kernel<<<grid, 256, SMEM_TOTAL>>>();

    final_kernel<<<1, 1024>>>((float*)d_out);
}

// round 4
// speedup vs baseline: 1.3611x; 1.1030x over previous
#include <cuda_runtime.h>
#include <cuda_bf16.h>
#include <mma.h>
#include <math.h>
#include <stdint.h>

using namespace nvcuda;

#define TOKENS_MAX 4096
#define D_DIM 1024
#define V_DIM 50257
#define BM 128
#define BN 256
#define BK 32
#define N_TILES 197                        // ceil(50257/256)
#define V_PAD (N_TILES * BN)               // 50432
#define KSTEPS (D_DIM / BK)                // 32
#define STAGES 4

#define LDS_PAD 40                          // smem row stride (elements)
#define A_STAGE_BYTES (BM * LDS_PAD * 2)    // 10240
#define B_STAGE_BYTES (BN * LDS_PAD * 2)    // 20480
#define STAGE_BYTES (A_STAGE_BYTES + B_STAGE_BYTES)  // 30720
#define CS_LD (BN + 8)                      // 264 floats
#define SMEM_TOTAL (BM * CS_LD * 4)         // 135168 > 4*STAGE_BYTES (122880)

// ---------------- device-global scratch ----------------
__device__ __align__(128) __nv_bfloat16 g_Wb[(size_t)V_PAD * D_DIM];
__device__ __align__(128) __nv_bfloat16 g_Ab[(size_t)TOKENS_MAX * D_DIM];
__device__ int   g_valid_idx[TOKENS_MAX];
__device__ int   g_tgt[TOKENS_MAX];
__device__ int   g_nvalid;
__device__ float g_sumexp[TOKENS_MAX];
__device__ float g_sumlogit[TOKENS_MAX];
__device__ float g_tlogit[TOKENS_MAX];

__device__ __forceinline__ uint32_t smem_u32(const void* p) {
    uint32_t a;
    asm("{ .reg .u64 t; cvta.to.shared.u64 t, %1; cvt.u32.u64 %0, t; }" : "=r"(a) : "l"(p));
    return a;
}
__device__ __forceinline__ void cp16(uint32_t dst, const void* src) {
    asm volatile("cp.async.cg.shared.global [%0], [%1], 16;\n" :: "r"(dst), "l"(src));
}

// ---------------- kernel 1: mask-dtype detect + compact valid tokens ----------------
__global__ void gather_kernel(const int* __restrict__ targets,
                              const unsigned char* __restrict__ masks_raw,
                              int n_tokens) {
    __shared__ int s_isu8;
    __shared__ int wsum[32];
    int tid = threadIdx.x;
    if (tid == 0) s_isu8 = 0;
    __syncthreads();

    int flag = 0;
    for (int i = tid; i < n_tokens; i += blockDim.x)
        if ((i & 3) != 0 && masks_raw[i] != 0) flag = 1;
    if (flag) atomicOr(&s_isu8, 1);
    __syncthreads();
    const bool isu8 = (s_isu8 != 0);
    const int* masks_i32 = (const int*)masks_raw;

    int C = (n_tokens + blockDim.x - 1) / blockDim.x;
    int start = tid * C;
    int end = min(start + C, n_tokens);
    int cnt = 0;
    for (int i = start; i < end; i++)
        cnt += isu8 ? (masks_raw[i] != 0) : (masks_i32[i] != 0);

    int lane = tid & 31, wid = tid >> 5;
    int v = cnt;
    #pragma unroll
    for (int o = 1; o < 32; o <<= 1) {
        int t = __shfl_up_sync(0xffffffffu, v, o);
        if (lane >= o) v += t;
    }
    if (lane == 31) wsum[wid] = v;
    __syncthreads();
    if (wid == 0) {
        int nw = blockDim.x >> 5;
        int w = (lane < nw) ? wsum[lane] : 0;
        #pragma unroll
        for (int o = 1; o < 32; o <<= 1) {
            int t = __shfl_up_sync(0xffffffffu, w, o);
            if (lane >= o) w += t;
        }
        wsum[lane] = w;
    }
    __syncthreads();
    int excl = v - cnt + (wid > 0 ? wsum[wid - 1] : 0);

    int off = excl;
    for (int i = start; i < end; i++) {
        bool mk = isu8 ? (masks_raw[i] != 0) : (masks_i32[i] != 0);
        if (mk) {
            g_valid_idx[off] = i;
            g_tgt[off] = targets[i];
            off++;
        }
    }
    if (tid == blockDim.x - 1) g_nvalid = excl + cnt;
}

// ---------------- kernel 2: gather + convert activations to bf16 ----------------
__global__ void build_a_kernel(const float* __restrict__ outputs) {
    int m = blockIdx.x;
    int tid = threadIdx.x;
    if (tid == 0) {
        g_sumexp[m] = 0.f;
        g_sumlogit[m] = 0.f;
        g_tlogit[m] = 0.f;
    }
    int nv = g_nvalid;
    __nv_bfloat16* dst = g_Ab + (size_t)m * D_DIM;
    if (m < nv) {
        const float* src = outputs + (size_t)g_valid_idx[m] * D_DIM;
        for (int i = tid * 4; i < D_DIM; i += blockDim.x * 4) {
            float4 v = *(const float4*)(src + i);
            *(__nv_bfloat162*)(dst + i)     = __floats2bfloat162_rn(v.x, v.y);
            *(__nv_bfloat162*)(dst + i + 2) = __floats2bfloat162_rn(v.z, v.w);
        }
    } else {
        __nv_bfloat162 z = __floats2bfloat162_rn(0.f, 0.f);
        for (int i = tid * 4; i < D_DIM; i += blockDim.x * 4) {
            *(__nv_bfloat162*)(dst + i)     = z;
            *(__nv_bfloat162*)(dst + i + 2) = z;
        }
    }
}

// ---------------- kernel 3: W fp32 -> bf16 (zero-pad to V_PAD) ----------------
__global__ void conv_w_kernel(const float* __restrict__ W) {
    long i = ((long)blockIdx.x * blockDim.x + threadIdx.x) * 4;
    const long nreal = (long)V_DIM * D_DIM;
    const long ntot  = (long)V_PAD * D_DIM;
    if (i < ntot) {
        if (i < nreal) {
            float4 v = *(const float4*)(W + i);
            *(__nv_bfloat162*)(g_Wb + i)     = __floats2bfloat162_rn(v.x, v.y);
            *(__nv_bfloat162*)(g_Wb + i + 2) = __floats2bfloat162_rn(v.z, v.w);
        } else {
            __nv_bfloat162 z = __floats2bfloat162_rn(0.f, 0.f);
            *(__nv_bfloat162*)(g_Wb + i)     = z;
            *(__nv_bfloat162*)(g_Wb + i + 2) = z;
        }
    }
}

// ---------------- kernel 4: 128x256x32 HMMA GEMM, 16 warps + epilogue ----------------
__global__ void __launch_bounds__(512, 1) gemm_epilogue_kernel() {
    extern __shared__ char smem[];
    uint32_t sb = smem_u32(smem);

    int nv = g_nvalid;
    int m0 = blockIdx.x * BM;
    if (m0 >= nv) return;
    int n0 = blockIdx.y * BN;

    int tid = threadIdx.x;
    int warp = tid >> 5;
    int wm = warp & 1;        // 2 M-groups: rows wm*64..+63
    int wn = warp >> 1;       // 8 N-groups: cols wn*32..+31

    // per-thread cp.async slots: A 1 chunk, B 2 chunks per stage (16B chunks)
    uint32_t adst, bdst[2];
    size_t   asrc, bsrc[2];
    const char* Ag = (const char*)g_Ab;
    const char* Wg = (const char*)g_Wb;
    {
        int c = tid;                       // 512 chunks = 128 rows x 4
        int row = c >> 2, cc = (c & 3) << 4;
        adst = (uint32_t)(row * (LDS_PAD * 2) + cc);
        asrc = (size_t)(m0 + row) * 2048 + cc;
    }
    #pragma unroll
    for (int i = 0; i < 2; i++) {
        int c = tid + i * 512;             // 1024 chunks = 256 rows x 4
        int row = c >> 2, cc = (c & 3) << 4;
        bdst[i] = (uint32_t)(row * (LDS_PAD * 2) + cc);
        bsrc[i] = (size_t)(n0 + row) * 2048 + cc;
    }

    wmma::fragment<wmma::accumulator, 16, 16, 16, float> acc[4][2];
    #pragma unroll
    for (int i = 0; i < 4; i++)
        #pragma unroll
        for (int j = 0; j < 2; j++)
            wmma::fill_fragment(acc[i][j], 0.0f);

    // prologue: 3 stages in flight
    #pragma unroll
    for (int s = 0; s < 3; s++) {
        uint32_t ab = sb + s * STAGE_BYTES;
        uint32_t bb = ab + A_STAGE_BYTES;
        size_t kb = (size_t)s * (BK * 2);
        cp16(ab + adst, Ag + asrc + kb);
        #pragma unroll
        for (int i = 0; i < 2; i++) cp16(bb + bdst[i], Wg + bsrc[i] + kb);
        asm volatile("cp.async.commit_group;" ::: "memory");
    }

    for (int j = 0; j < KSTEPS; j++) {
        asm volatile("cp.async.wait_group 2;" ::: "memory");
        __syncthreads();

        // prefetch stage j+3
        if (j + 3 < KSTEPS) {
            int s = (j + 3) % STAGES;
            uint32_t ab = sb + s * STAGE_BYTES;
            uint32_t bb = ab + A_STAGE_BYTES;
            size_t kb = (size_t)(j + 3) * (BK * 2);
            cp16(ab + adst, Ag + asrc + kb);
            #pragma unroll
            for (int i = 0; i < 2; i++) cp16(bb + bdst[i], Wg + bsrc[i] + kb);
        }
        asm volatile("cp.async.commit_group;" ::: "memory");

        // compute stage j
        int s = j % STAGES;
        const __nv_bfloat16* As = (const __nv_bfloat16*)(smem + s * STAGE_BYTES);
        const __nv_bfloat16* Bs = (const __nv_bfloat16*)(smem + s * STAGE_BYTES + A_STAGE_BYTES);
        #pragma unroll
        for (int kk = 0; kk < BK; kk += 16) {
            wmma::fragment<wmma::matrix_a, 16, 16, 16, __nv_bfloat16, wmma::row_major> a[4];
            wmma::fragment<wmma::matrix_b, 16, 16, 16, __nv_bfloat16, wmma::col_major> b[2];
            #pragma unroll
            for (int i = 0; i < 4; i++)
                wmma::load_matrix_sync(a[i], As + (wm * 64 + i * 16) * LDS_PAD + kk, LDS_PAD);
            #pragma unroll
            for (int jj = 0; jj < 2; jj++)
                wmma::load_matrix_sync(b[jj], Bs + (wn * 32 + jj * 16) * LDS_PAD + kk, LDS_PAD);
            #pragma unroll
            for (int i = 0; i < 4; i++)
                #pragma unroll
                for (int jj = 0; jj < 2; jj++)
                    wmma::mma_sync(acc[i][jj], a[i], b[jj], acc[i][jj]);
        }
        __syncthreads();
    }

    // ---- epilogue: stage full C tile (fp32) in smem, reduce per row ----
    float* Cs = (float*)smem;
    #pragma unroll
    for (int i = 0; i < 4; i++)
        #pragma unroll
        for (int jj = 0; jj < 2; jj++)
            wmma::store_matrix_sync(Cs + (wm * 64 + i * 16) * CS_LD + wn * 32 + jj * 16,
                                    acc[i][jj], CS_LD, wmma::mem_row_major);
    __syncthreads();

    int row = tid >> 2;            // 128 rows, 4 threads each
    int q = tid & 3;
    int gm = m0 + row;
    const float* crow = Cs + row * CS_LD + q * 64;
    int c0 = n0 + q * 64;
    float se = 0.f, sl = 0.f;
    #pragma unroll 4
    for (int c = 0; c < 64; c++) {
        int col = c0 + c;
        if (col < V_DIM) {
            float v = crow[c];
            se += __expf(v);
            sl += v;
        }
    }
    se += __shfl_xor_sync(0xffffffffu, se, 1);
    sl += __shfl_xor_sync(0xffffffffu, sl, 1);
    se += __shfl_xor_sync(0xffffffffu, se, 2);
    sl += __shfl_xor_sync(0xffffffffu, sl, 2);
    if (q == 0 && gm < nv) {
        atomicAdd(&g_sumexp[gm], se);
        atomicAdd(&g_sumlogit[gm], sl);
        int t = g_tgt[gm];
        if (t >= n0 && t < n0 + BN)
            g_tlogit[gm] = Cs[row * CS_LD + (t - n0)];
    }
}

// ---------------- kernel 5: final scalar reduction ----------------
__global__ void final_kernel(float* __restrict__ out) {
    __shared__ double s_n[32], s_s[32];
    int tid = threadIdx.x;
    int nv = g_nvalid;
    double nll = 0.0, slp = 0.0;
    for (int m = tid; m < nv; m += blockDim.x) {
        float lse = logf(g_sumexp[m]);
        nll += (double)lse - (double)g_tlogit[m];
        slp += (double)g_sumlogit[m] - (double)V_DIM * (double)lse;
    }
    #pragma unroll
    for (int o = 16; o; o >>= 1) {
        nll += __shfl_down_sync(0xffffffffu, nll, o);
        slp += __shfl_down_sync(0xffffffffu, slp, o);
    }
    if ((tid & 31) == 0) { s_n[tid >> 5] = nll; s_s[tid >> 5] = slp; }
    __syncthreads();
    if (tid < 32) {
        int nw = blockDim.x >> 5;
        nll = (tid < nw) ? s_n[tid] : 0.0;
        slp = (tid < nw) ? s_s[tid] : 0.0;
        #pragma unroll
        for (int o = 16; o; o >>= 1) {
            nll += __shfl_down_sync(0xffffffffu, nll, o);
            slp += __shfl_down_sync(0xffffffffu, slp, o);
        }
        if (tid == 0) {
            double n = (double)nv;
            double loss = 0.9 * (nll / n) - 0.1 * (slp / (n * (double)V_DIM));
            out[0] = (float)loss;
        }
    }
}

// ---------------- launch ----------------
extern "C" void kernel_launch(void* const* d_in, const int* in_sizes, int n_in,
                              void* d_out, int out_size) {
    const int*           targets = (const int*)d_in[0];
    const unsigned char* masks   = (const unsigned char*)d_in[1];
    const float*         outputs = (const float*)d_in[2];
    const float*         W       = (const float*)d_in[3];
    int n_tokens = in_sizes[0];   // 4096

    static int s_attr_done = 0;
    if (!s_attr_done) {
        cudaFuncSetAttribute(gemm_epilogue_kernel,
                             cudaFuncAttributeMaxDynamicSharedMemorySize, SMEM_TOTAL);
        s_attr_done = 1;
    }

    gather_kernel<<<1, 1024>>>(targets, masks, n_tokens);
    build_a_kernel<<<n_tokens, 256>>>(outputs);

    long ntot = (long)V_PAD * D_DIM;
    int conv_blocks = (int)((ntot / 4 + 255) / 256);
    conv_w_kernel<<<conv_blocks, 256>>>(W);

    dim3 grid((TOKENS_MAX + BM - 1) / BM, N_TILES);
    gemm_epilogue_kernel<<<grid, 512, SMEM_TOTAL>>>();

    final_kernel<<<1, 1024>>>((float*)d_out);
}

// round 5
// speedup vs baseline: 1.5089x; 1.1086x over previous
#include <cuda_runtime.h>
#include <cuda_bf16.h>
#include <mma.h>
#include <math.h>
#include <stdint.h>

using namespace nvcuda;

#define TOKENS_MAX 4096
#define D_DIM 1024
#define V_DIM 50257
#define BM 128
#define BN 128
#define BK 32
#define N_TILES 393                        // ceil(50257/128)
#define V_PAD (N_TILES * BN)               // 50304
#define KSTEPS (D_DIM / BK)                // 32
#define STAGES 4

#define LDS_PAD 40                          // smem row stride (elements)
#define A_STAGE_BYTES (BM * LDS_PAD * 2)    // 10240
#define B_STAGE_BYTES (BN * LDS_PAD * 2)    // 10240
#define STAGE_BYTES (A_STAGE_BYTES + B_STAGE_BYTES)  // 20480
#define CS_LD (BN + 8)                      // 136 floats
#define SMEM_TOTAL (STAGES * STAGE_BYTES)   // 81920 > C staging (128*136*4=69632)

// ---------------- device-global scratch ----------------
__device__ __align__(128) __nv_bfloat16 g_Wb[(size_t)V_PAD * D_DIM];
__device__ __align__(128) __nv_bfloat16 g_Ab[(size_t)TOKENS_MAX * D_DIM];
__device__ int   g_valid_idx[TOKENS_MAX];
__device__ int   g_tgt[TOKENS_MAX];
__device__ int   g_nvalid;
__device__ float g_sumexp[TOKENS_MAX];
__device__ float g_sumlogit[TOKENS_MAX];
__device__ float g_tlogit[TOKENS_MAX];

__device__ __forceinline__ uint32_t smem_u32(const void* p) {
    uint32_t a;
    asm("{ .reg .u64 t; cvta.to.shared.u64 t, %1; cvt.u32.u64 %0, t; }" : "=r"(a) : "l"(p));
    return a;
}
__device__ __forceinline__ void cp16(uint32_t dst, const void* src) {
    asm volatile("cp.async.cg.shared.global [%0], [%1], 16;\n" :: "r"(dst), "l"(src));
}

// ---------------- kernel 1: mask-dtype detect + compact valid tokens ----------------
__global__ void gather_kernel(const int* __restrict__ targets,
                              const unsigned char* __restrict__ masks_raw,
                              int n_tokens) {
    __shared__ int s_isu8;
    __shared__ int wsum[32];
    int tid = threadIdx.x;
    if (tid == 0) s_isu8 = 0;
    __syncthreads();

    int flag = 0;
    for (int i = tid; i < n_tokens; i += blockDim.x)
        if ((i & 3) != 0 && masks_raw[i] != 0) flag = 1;
    if (flag) atomicOr(&s_isu8, 1);
    __syncthreads();
    const bool isu8 = (s_isu8 != 0);
    const int* masks_i32 = (const int*)masks_raw;

    int C = (n_tokens + blockDim.x - 1) / blockDim.x;
    int start = tid * C;
    int end = min(start + C, n_tokens);
    int cnt = 0;
    for (int i = start; i < end; i++)
        cnt += isu8 ? (masks_raw[i] != 0) : (masks_i32[i] != 0);

    int lane = tid & 31, wid = tid >> 5;
    int v = cnt;
    #pragma unroll
    for (int o = 1; o < 32; o <<= 1) {
        int t = __shfl_up_sync(0xffffffffu, v, o);
        if (lane >= o) v += t;
    }
    if (lane == 31) wsum[wid] = v;
    __syncthreads();
    if (wid == 0) {
        int nw = blockDim.x >> 5;
        int w = (lane < nw) ? wsum[lane] : 0;
        #pragma unroll
        for (int o = 1; o < 32; o <<= 1) {
            int t = __shfl_up_sync(0xffffffffu, w, o);
            if (lane >= o) w += t;
        }
        wsum[lane] = w;
    }
    __syncthreads();
    int excl = v - cnt + (wid > 0 ? wsum[wid - 1] : 0);

    int off = excl;
    for (int i = start; i < end; i++) {
        bool mk = isu8 ? (masks_raw[i] != 0) : (masks_i32[i] != 0);
        if (mk) {
            g_valid_idx[off] = i;
            g_tgt[off] = targets[i];
            off++;
        }
    }
    if (tid == blockDim.x - 1) g_nvalid = excl + cnt;
}

// ---------------- kernel 2: gather + convert activations to bf16 ----------------
__global__ void build_a_kernel(const float* __restrict__ outputs) {
    int m = blockIdx.x;
    int tid = threadIdx.x;
    if (tid == 0) {
        g_sumexp[m] = 0.f;
        g_sumlogit[m] = 0.f;
        g_tlogit[m] = 0.f;
    }
    int nv = g_nvalid;
    __nv_bfloat16* dst = g_Ab + (size_t)m * D_DIM;
    if (m < nv) {
        const float* src = outputs + (size_t)g_valid_idx[m] * D_DIM;
        for (int i = tid * 4; i < D_DIM; i += blockDim.x * 4) {
            float4 v = *(const float4*)(src + i);
            *(__nv_bfloat162*)(dst + i)     = __floats2bfloat162_rn(v.x, v.y);
            *(__nv_bfloat162*)(dst + i + 2) = __floats2bfloat162_rn(v.z, v.w);
        }
    } else {
        __nv_bfloat162 z = __floats2bfloat162_rn(0.f, 0.f);
        for (int i = tid * 4; i < D_DIM; i += blockDim.x * 4) {
            *(__nv_bfloat162*)(dst + i)     = z;
            *(__nv_bfloat162*)(dst + i + 2) = z;
        }
    }
}

// ---------------- kernel 3: W fp32 -> bf16 (zero-pad to V_PAD) ----------------
__global__ void conv_w_kernel(const float* __restrict__ W) {
    long i = ((long)blockIdx.x * blockDim.x + threadIdx.x) * 4;
    const long nreal = (long)V_DIM * D_DIM;
    const long ntot  = (long)V_PAD * D_DIM;
    if (i < ntot) {
        if (i < nreal) {
            float4 v = *(const float4*)(W + i);
            *(__nv_bfloat162*)(g_Wb + i)     = __floats2bfloat162_rn(v.x, v.y);
            *(__nv_bfloat162*)(g_Wb + i + 2) = __floats2bfloat162_rn(v.z, v.w);
        } else {
            __nv_bfloat162 z = __floats2bfloat162_rn(0.f, 0.f);
            *(__nv_bfloat162*)(g_Wb + i)     = z;
            *(__nv_bfloat162*)(g_Wb + i + 2) = z;
        }
    }
}

// ---------------- kernel 4: 128x128x32 HMMA GEMM, 2 CTAs/SM + epilogue ----------------
__global__ void __launch_bounds__(256, 2) gemm_epilogue_kernel() {
    extern __shared__ char smem[];
    uint32_t sb = smem_u32(smem);

    int nv = g_nvalid;
    int m0 = blockIdx.x * BM;
    if (m0 >= nv) return;
    int n0 = blockIdx.y * BN;

    int tid = threadIdx.x;
    int warp = tid >> 5;
    int wm = warp & 1;        // 2 M-groups: rows wm*64..+63
    int wn = warp >> 1;       // 4 N-groups: cols wn*32..+31

    // per-thread cp.async slots: A 2 chunks, B 2 chunks per stage (16B chunks)
    // stage layout: A = 128 rows x 64B (4 chunks/row), B same
    uint32_t adst[2], bdst[2];
    size_t   asrc[2], bsrc[2];
    const char* Ag = (const char*)g_Ab;
    const char* Wg = (const char*)g_Wb;
    #pragma unroll
    for (int i = 0; i < 2; i++) {
        int c = tid + i * 256;             // 512 chunks = 128 rows x 4
        int row = c >> 2, cc = (c & 3) << 4;
        adst[i] = (uint32_t)(row * (LDS_PAD * 2) + cc);
        asrc[i] = (size_t)(m0 + row) * 2048 + cc;
        bdst[i] = adst[i];
        bsrc[i] = (size_t)(n0 + row) * 2048 + cc;
    }

    wmma::fragment<wmma::accumulator, 16, 16, 16, float> acc[4][2];
    #pragma unroll
    for (int i = 0; i < 4; i++)
        #pragma unroll
        for (int j = 0; j < 2; j++)
            wmma::fill_fragment(acc[i][j], 0.0f);

    // prologue: 3 stages in flight
    #pragma unroll
    for (int s = 0; s < 3; s++) {
        uint32_t ab = sb + s * STAGE_BYTES;
        uint32_t bb = ab + A_STAGE_BYTES;
        size_t kb = (size_t)s * (BK * 2);
        #pragma unroll
        for (int i = 0; i < 2; i++) {
            cp16(ab + adst[i], Ag + asrc[i] + kb);
            cp16(bb + bdst[i], Wg + bsrc[i] + kb);
        }
        asm volatile("cp.async.commit_group;" ::: "memory");
    }

    for (int j = 0; j < KSTEPS; j++) {
        asm volatile("cp.async.wait_group 2;" ::: "memory");
        __syncthreads();   // single barrier per K-step

        // prefetch stage j+3 (writes stage (j-1)%4, last read before this barrier)
        if (j + 3 < KSTEPS) {
            int s = (j + 3) % STAGES;
            uint32_t ab = sb + s * STAGE_BYTES;
            uint32_t bb = ab + A_STAGE_BYTES;
            size_t kb = (size_t)(j + 3) * (BK * 2);
            #pragma unroll
            for (int i = 0; i < 2; i++) {
                cp16(ab + adst[i], Ag + asrc[i] + kb);
                cp16(bb + bdst[i], Wg + bsrc[i] + kb);
            }
        }
        asm volatile("cp.async.commit_group;" ::: "memory");

        // compute stage j
        int s = j % STAGES;
        const __nv_bfloat16* As = (const __nv_bfloat16*)(smem + s * STAGE_BYTES);
        const __nv_bfloat16* Bs = (const __nv_bfloat16*)(smem + s * STAGE_BYTES + A_STAGE_BYTES);
        #pragma unroll
        for (int kk = 0; kk < BK; kk += 16) {
            wmma::fragment<wmma::matrix_a, 16, 16, 16, __nv_bfloat16, wmma::row_major> a[4];
            wmma::fragment<wmma::matrix_b, 16, 16, 16, __nv_bfloat16, wmma::col_major> b[2];
            #pragma unroll
            for (int i = 0; i < 4; i++)
                wmma::load_matrix_sync(a[i], As + (wm * 64 + i * 16) * LDS_PAD + kk, LDS_PAD);
            #pragma unroll
            for (int jj = 0; jj < 2; jj++)
                wmma::load_matrix_sync(b[jj], Bs + (wn * 32 + jj * 16) * LDS_PAD + kk, LDS_PAD);
            #pragma unroll
            for (int i = 0; i < 4; i++)
                #pragma unroll
                for (int jj = 0; jj < 2; jj++)
                    wmma::mma_sync(acc[i][jj], a[i], b[jj], acc[i][jj]);
        }
    }
    __syncthreads();   // protect smem reuse for C staging

    // ---- epilogue: stage C tile (fp32) in smem, reduce per row ----
    float* Cs = (float*)smem;
    #pragma unroll
    for (int i = 0; i < 4; i++)
        #pragma unroll
        for (int jj = 0; jj < 2; jj++)
            wmma::store_matrix_sync(Cs + (wm * 64 + i * 16) * CS_LD + wn * 32 + jj * 16,
                                    acc[i][jj], CS_LD, wmma::mem_row_major);
    __syncthreads();

    int row = tid >> 1;            // 128 rows, 2 threads each
    int half = tid & 1;
    int gm = m0 + row;
    const float* crow = Cs + row * CS_LD + half * 64;
    int c0 = n0 + half * 64;
    float se = 0.f, sl = 0.f;
    #pragma unroll 4
    for (int c = 0; c < 64; c++) {
        int col = c0 + c;
        if (col < V_DIM) {
            float v = crow[c];
            se += __expf(v);
            sl += v;
        }
    }
    se += __shfl_xor_sync(0xffffffffu, se, 1);
    sl += __shfl_xor_sync(0xffffffffu, sl, 1);
    if (half == 0 && gm < nv) {
        atomicAdd(&g_sumexp[gm], se);
        atomicAdd(&g_sumlogit[gm], sl);
        int t = g_tgt[gm];
        if (t >= n0 && t < n0 + BN)
            g_tlogit[gm] = Cs[row * CS_LD + (t - n0)];
    }
}

// ---------------- kernel 5: final scalar reduction ----------------
__global__ void final_kernel(float* __restrict__ out) {
    __shared__ double s_n[32], s_s[32];
    int tid = threadIdx.x;
    int nv = g_nvalid;
    double nll = 0.0, slp = 0.0;
    for (int m = tid; m < nv; m += blockDim.x) {
        float lse = logf(g_sumexp[m]);
        nll += (double)lse - (double)g_tlogit[m];
        slp += (double)g_sumlogit[m] - (double)V_DIM * (double)lse;
    }
    #pragma unroll
    for (int o = 16; o; o >>= 1) {
        nll += __shfl_down_sync(0xffffffffu, nll, o);
        slp += __shfl_down_sync(0xffffffffu, slp, o);
    }
    if ((tid & 31) == 0) { s_n[tid >> 5] = nll; s_s[tid >> 5] = slp; }
    __syncthreads();
    if (tid < 32) {
        int nw = blockDim.x >> 5;
        nll = (tid < nw) ? s_n[tid] : 0.0;
        slp = (tid < nw) ? s_s[tid] : 0.0;
        #pragma unroll
        for (int o = 16; o; o >>= 1) {
            nll += __shfl_down_sync(0xffffffffu, nll, o);
            slp += __shfl_down_sync(0xffffffffu, slp, o);
        }
        if (tid == 0) {
            double n = (double)nv;
            double loss = 0.9 * (nll / n) - 0.1 * (slp / (n * (double)V_DIM));
            out[0] = (float)loss;
        }
    }
}

// ---------------- launch ----------------
extern "C" void kernel_launch(void* const* d_in, const int* in_sizes, int n_in,
                              void* d_out, int out_size) {
    const int*           targets = (const int*)d_in[0];
    const unsigned char* masks   = (const unsigned char*)d_in[1];
    const float*         outputs = (const float*)d_in[2];
    const float*         W       = (const float*)d_in[3];
    int n_tokens = in_sizes[0];   // 4096

    static int s_attr_done = 0;
    if (!s_attr_done) {
        cudaFuncSetAttribute(gemm_epilogue_kernel,
                             cudaFuncAttributeMaxDynamicSharedMemorySize, SMEM_TOTAL);
        s_attr_done = 1;
    }

    gather_kernel<<<1, 1024>>>(targets, masks, n_tokens);
    build_a_kernel<<<n_tokens, 256>>>(outputs);

    long ntot = (long)V_PAD * D_DIM;
    int conv_blocks = (int)((ntot / 4 + 255) / 256);
    conv_w_kernel<<<conv_blocks, 256>>>(W);

    dim3 grid((TOKENS_MAX + BM - 1) / BM, N_TILES);
    gemm_epilogue_kernel<<<grid, 256, SMEM_TOTAL>>>();

    final_kernel<<<1, 1024>>>((float*)d_out);
}

// round 6
// speedup vs baseline: 1.6212x; 1.0744x over previous
#include <cuda_runtime.h>
#include <cuda_bf16.h>
#include <mma.h>
#include <math.h>
#include <stdint.h>

using namespace nvcuda;

#define TOKENS_MAX 4096
#define D_DIM 1024
#define V_DIM 50257
#define BM 128
#define BN 128
#define BK 32
#define N_TILES 393                        // ceil(50257/128)
#define V_PAD (N_TILES * BN)               // 50304
#define KSTEPS (D_DIM / BK)                // 32
#define STAGES 4

#define LDS_PAD 40                          // smem row stride (elements)
#define A_STAGE_BYTES (BM * LDS_PAD * 2)    // 10240
#define B_STAGE_BYTES (BN * LDS_PAD * 2)    // 10240
#define STAGE_BYTES (A_STAGE_BYTES + B_STAGE_BYTES)  // 20480
#define CS_LD 132                           // fp32 elems; %4==0 for wmma, bank-rotating
#define SMEM_TOTAL (STAGES * STAGE_BYTES)   // 81920 > C staging (128*132*4=67584)

// ---------------- device-global scratch ----------------
__device__ __align__(128) __nv_bfloat16 g_Wb[(size_t)V_PAD * D_DIM];
__device__ __align__(128) __nv_bfloat16 g_Ab[(size_t)TOKENS_MAX * D_DIM];
__device__ int   g_valid_idx[TOKENS_MAX];
__device__ int   g_tgt[TOKENS_MAX];
__device__ int   g_nvalid;
__device__ float g_sumexp[TOKENS_MAX];
__device__ float g_sumlogit[TOKENS_MAX];
__device__ float g_tlogit[TOKENS_MAX];

__device__ __forceinline__ uint32_t smem_u32(const void* p) {
    uint32_t a;
    asm("{ .reg .u64 t; cvta.to.shared.u64 t, %1; cvt.u32.u64 %0, t; }" : "=r"(a) : "l"(p));
    return a;
}
__device__ __forceinline__ void cp16(uint32_t dst, const void* src) {
    asm volatile("cp.async.cg.shared.global [%0], [%1], 16;\n" :: "r"(dst), "l"(src));
}

// ---------------- kernel 1: mask-dtype detect + compact valid tokens ----------------
__global__ void gather_kernel(const int* __restrict__ targets,
                              const unsigned char* __restrict__ masks_raw,
                              int n_tokens) {
    __shared__ int s_isu8;
    __shared__ int wsum[32];
    int tid = threadIdx.x;
    if (tid == 0) s_isu8 = 0;
    __syncthreads();

    int flag = 0;
    for (int i = tid; i < n_tokens; i += blockDim.x)
        if ((i & 3) != 0 && masks_raw[i] != 0) flag = 1;
    if (flag) atomicOr(&s_isu8, 1);
    __syncthreads();
    const bool isu8 = (s_isu8 != 0);
    const int* masks_i32 = (const int*)masks_raw;

    int C = (n_tokens + blockDim.x - 1) / blockDim.x;
    int start = tid * C;
    int end = min(start + C, n_tokens);
    int cnt = 0;
    for (int i = start; i < end; i++)
        cnt += isu8 ? (masks_raw[i] != 0) : (masks_i32[i] != 0);

    int lane = tid & 31, wid = tid >> 5;
    int v = cnt;
    #pragma unroll
    for (int o = 1; o < 32; o <<= 1) {
        int t = __shfl_up_sync(0xffffffffu, v, o);
        if (lane >= o) v += t;
    }
    if (lane == 31) wsum[wid] = v;
    __syncthreads();
    if (wid == 0) {
        int nw = blockDim.x >> 5;
        int w = (lane < nw) ? wsum[lane] : 0;
        #pragma unroll
        for (int o = 1; o < 32; o <<= 1) {
            int t = __shfl_up_sync(0xffffffffu, w, o);
            if (lane >= o) w += t;
        }
        wsum[lane] = w;
    }
    __syncthreads();
    int excl = v - cnt + (wid > 0 ? wsum[wid - 1] : 0);

    int off = excl;
    for (int i = start; i < end; i++) {
        bool mk = isu8 ? (masks_raw[i] != 0) : (masks_i32[i] != 0);
        if (mk) {
            g_valid_idx[off] = i;
            g_tgt[off] = targets[i];
            off++;
        }
    }
    if (tid == blockDim.x - 1) g_nvalid = excl + cnt;
}

// ---------------- kernel 2: gather + convert activations to bf16 ----------------
__global__ void build_a_kernel(const float* __restrict__ outputs) {
    int m = blockIdx.x;
    int tid = threadIdx.x;
    if (tid == 0) {
        g_sumexp[m] = 0.f;
        g_sumlogit[m] = 0.f;
        g_tlogit[m] = 0.f;
    }
    int nv = g_nvalid;
    __nv_bfloat16* dst = g_Ab + (size_t)m * D_DIM;
    if (m < nv) {
        const float* src = outputs + (size_t)g_valid_idx[m] * D_DIM;
        for (int i = tid * 4; i < D_DIM; i += blockDim.x * 4) {
            float4 v = *(const float4*)(src + i);
            *(__nv_bfloat162*)(dst + i)     = __floats2bfloat162_rn(v.x, v.y);
            *(__nv_bfloat162*)(dst + i + 2) = __floats2bfloat162_rn(v.z, v.w);
        }
    } else {
        __nv_bfloat162 z = __floats2bfloat162_rn(0.f, 0.f);
        for (int i = tid * 4; i < D_DIM; i += blockDim.x * 4) {
            *(__nv_bfloat162*)(dst + i)     = z;
            *(__nv_bfloat162*)(dst + i + 2) = z;
        }
    }
}

// ---------------- kernel 3: W fp32 -> bf16 (zero-pad to V_PAD) ----------------
__global__ void conv_w_kernel(const float* __restrict__ W) {
    long i = ((long)blockIdx.x * blockDim.x + threadIdx.x) * 4;
    const long nreal = (long)V_DIM * D_DIM;
    const long ntot  = (long)V_PAD * D_DIM;
    if (i < ntot) {
        if (i < nreal) {
            float4 v = *(const float4*)(W + i);
            *(__nv_bfloat162*)(g_Wb + i)     = __floats2bfloat162_rn(v.x, v.y);
            *(__nv_bfloat162*)(g_Wb + i + 2) = __floats2bfloat162_rn(v.z, v.w);
        } else {
            __nv_bfloat162 z = __floats2bfloat162_rn(0.f, 0.f);
            *(__nv_bfloat162*)(g_Wb + i)     = z;
            *(__nv_bfloat162*)(g_Wb + i + 2) = z;
        }
    }
}

// ---------------- kernel 4: 128x128x32 HMMA, warp tile 64x64, 2 CTAs/SM ----------------
__global__ void __launch_bounds__(128, 2) gemm_epilogue_kernel() {
    extern __shared__ char smem[];
    uint32_t sb = smem_u32(smem);

    int nv = g_nvalid;
    int m0 = blockIdx.x * BM;
    if (m0 >= nv) return;
    int n0 = blockIdx.y * BN;

    int tid = threadIdx.x;
    int warp = tid >> 5, lane = tid & 31;
    int wm = warp & 1;        // rows wm*64..+63
    int wn = warp >> 1;       // cols wn*64..+63

    // per-thread cp.async slots: 4 A chunks + 4 B chunks per stage (16B chunks)
    uint32_t adst[4], bdst[4];
    size_t   asrc[4], bsrc[4];
    const char* Ag = (const char*)g_Ab;
    const char* Wg = (const char*)g_Wb;
    #pragma unroll
    for (int i = 0; i < 4; i++) {
        int c = tid + i * 128;             // 512 chunks = 128 rows x 4
        int row = c >> 2, cc = (c & 3) << 4;
        adst[i] = (uint32_t)(row * (LDS_PAD * 2) + cc);
        asrc[i] = (size_t)(m0 + row) * 2048 + cc;
        bdst[i] = adst[i];
        bsrc[i] = (size_t)(n0 + row) * 2048 + cc;
    }

    wmma::fragment<wmma::accumulator, 16, 16, 16, float> acc[4][4];
    #pragma unroll
    for (int i = 0; i < 4; i++)
        #pragma unroll
        for (int j = 0; j < 4; j++)
            wmma::fill_fragment(acc[i][j], 0.0f);

    // prologue: 3 stages in flight
    #pragma unroll
    for (int s = 0; s < 3; s++) {
        uint32_t ab = sb + s * STAGE_BYTES;
        uint32_t bb = ab + A_STAGE_BYTES;
        size_t kb = (size_t)s * (BK * 2);
        #pragma unroll
        for (int i = 0; i < 4; i++) {
            cp16(ab + adst[i], Ag + asrc[i] + kb);
            cp16(bb + bdst[i], Wg + bsrc[i] + kb);
        }
        asm volatile("cp.async.commit_group;" ::: "memory");
    }

    for (int j = 0; j < KSTEPS; j++) {
        asm volatile("cp.async.wait_group 2;" ::: "memory");
        __syncthreads();   // single barrier per K-step

        // prefetch stage j+3 (writes stage (j-1)%4, already consumed)
        if (j + 3 < KSTEPS) {
            int s = (j + 3) % STAGES;
            uint32_t ab = sb + s * STAGE_BYTES;
            uint32_t bb = ab + A_STAGE_BYTES;
            size_t kb = (size_t)(j + 3) * (BK * 2);
            #pragma unroll
            for (int i = 0; i < 4; i++) {
                cp16(ab + adst[i], Ag + asrc[i] + kb);
                cp16(bb + bdst[i], Wg + bsrc[i] + kb);
            }
        }
        asm volatile("cp.async.commit_group;" ::: "memory");

        // compute stage j: warp tile 64x64
        int s = j % STAGES;
        const __nv_bfloat16* As = (const __nv_bfloat16*)(smem + s * STAGE_BYTES);
        const __nv_bfloat16* Bs = (const __nv_bfloat16*)(smem + s * STAGE_BYTES + A_STAGE_BYTES);
        #pragma unroll
        for (int kk = 0; kk < BK; kk += 16) {
            wmma::fragment<wmma::matrix_a, 16, 16, 16, __nv_bfloat16, wmma::row_major> a[4];
            wmma::fragment<wmma::matrix_b, 16, 16, 16, __nv_bfloat16, wmma::col_major> b[4];
            #pragma unroll
            for (int i = 0; i < 4; i++)
                wmma::load_matrix_sync(a[i], As + (wm * 64 + i * 16) * LDS_PAD + kk, LDS_PAD);
            #pragma unroll
            for (int jj = 0; jj < 4; jj++)
                wmma::load_matrix_sync(b[jj], Bs + (wn * 64 + jj * 16) * LDS_PAD + kk, LDS_PAD);
            #pragma unroll
            for (int i = 0; i < 4; i++)
                #pragma unroll
                for (int jj = 0; jj < 4; jj++)
                    wmma::mma_sync(acc[i][jj], a[i], b[jj], acc[i][jj]);
        }
    }
    __syncthreads();   // protect smem reuse for C staging

    // ---- epilogue: stage C tile (fp32) in smem, reduce per row ----
    float* Cs = (float*)smem;
    #pragma unroll
    for (int i = 0; i < 4; i++)
        #pragma unroll
        for (int jj = 0; jj < 4; jj++)
            wmma::store_matrix_sync(Cs + (wm * 64 + i * 16) * CS_LD + wn * 64 + jj * 16,
                                    acc[i][jj], CS_LD, wmma::mem_row_major);
    __syncthreads();

    // one thread per row; column rotation (lane+k)&127 -> bank (5*lane+k)%32, conflict-free
    int row = tid;
    int gm = m0 + row;
    const float* crow = Cs + row * CS_LD;
    float se = 0.f, sl = 0.f;
    #pragma unroll 8
    for (int k = 0; k < 128; k++) {
        int c = (lane + k) & 127;
        int col = n0 + c;
        if (col < V_DIM) {
            float v = crow[c];
            se += __expf(v);
            sl += v;
        }
    }
    if (gm < nv) {
        atomicAdd(&g_sumexp[gm], se);
        atomicAdd(&g_sumlogit[gm], sl);
        int t = g_tgt[gm];
        if (t >= n0 && t < n0 + BN)
            g_tlogit[gm] = crow[t - n0];
    }
}

// ---------------- kernel 5: final scalar reduction ----------------
__global__ void final_kernel(float* __restrict__ out) {
    __shared__ double s_n[32], s_s[32];
    int tid = threadIdx.x;
    int nv = g_nvalid;
    double nll = 0.0, slp = 0.0;
    for (int m = tid; m < nv; m += blockDim.x) {
        float lse = logf(g_sumexp[m]);
        nll += (double)lse - (double)g_tlogit[m];
        slp += (double)g_sumlogit[m] - (double)V_DIM * (double)lse;
    }
    #pragma unroll
    for (int o = 16; o; o >>= 1) {
        nll += __shfl_down_sync(0xffffffffu, nll, o);
        slp += __shfl_down_sync(0xffffffffu, slp, o);
    }
    if ((tid & 31) == 0) { s_n[tid >> 5] = nll; s_s[tid >> 5] = slp; }
    __syncthreads();
    if (tid < 32) {
        int nw = blockDim.x >> 5;
        nll = (tid < nw) ? s_n[tid] : 0.0;
        slp = (tid < nw) ? s_s[tid] : 0.0;
        #pragma unroll
        for (int o = 16; o; o >>= 1) {
            nll += __shfl_down_sync(0xffffffffu, nll, o);
            slp += __shfl_down_sync(0xffffffffu, slp, o);
        }
        if (tid == 0) {
            double n = (double)nv;
            double loss = 0.9 * (nll / n) - 0.1 * (slp / (n * (double)V_DIM));
            out[0] = (float)loss;
        }
    }
}

// ---------------- launch ----------------
extern "C" void kernel_launch(void* const* d_in, const int* in_sizes, int n_in,
                              void* d_out, int out_size) {
    const int*           targets = (const int*)d_in[0];
    const unsigned char* masks   = (const unsigned char*)d_in[1];
    const float*         outputs = (const float*)d_in[2];
    const float*         W       = (const float*)d_in[3];
    int n_tokens = in_sizes[0];   // 4096

    static int s_attr_done = 0;
    if (!s_attr_done) {
        cudaFuncSetAttribute(gemm_epilogue_kernel,
                             cudaFuncAttributeMaxDynamicSharedMemorySize, SMEM_TOTAL);
        s_attr_done = 1;
    }

    gather_kernel<<<1, 1024>>>(targets, masks, n_tokens);
    build_a_kernel<<<n_tokens, 256>>>(outputs);

    long ntot = (long)V_PAD * D_DIM;
    int conv_blocks = (int)((ntot / 4 + 255) / 256);
    conv_w_kernel<<<conv_blocks, 256>>>(W);

    dim3 grid((TOKENS_MAX + BM - 1) / BM, N_TILES);
    gemm_epilogue_kernel<<<grid, 128, SMEM_TOTAL>>>();

    final_kernel<<<1, 1024>>>((float*)d_out);
}

// round 7
// speedup vs baseline: 1.7464x; 1.0772x over previous
#include <cuda_runtime.h>
#include <cuda_bf16.h>
#include <mma.h>
#include <math.h>
#include <stdint.h>

using namespace nvcuda;

#define TOKENS_MAX 4096
#define D_DIM 1024
#define V_DIM 50257
#define BM 128
#define BN 128
#define BK 64
#define N_TILES 393                        // ceil(50257/128)
#define V_PAD (N_TILES * BN)               // 50304
#define KSTEPS (D_DIM / BK)                // 16
#define STAGES 3

#define LDS_PAD 72                          // elems/row (144B): ldmatrix banks 4(r+c)%32, clean
#define A_STAGE_BYTES (BM * LDS_PAD * 2)    // 18432
#define B_STAGE_BYTES (BN * LDS_PAD * 2)    // 18432
#define STAGE_BYTES (A_STAGE_BYTES + B_STAGE_BYTES)  // 36864
#define CS_LD 132                           // fp32 elems; %4==0 for wmma, bank-rotating
#define SMEM_TOTAL (STAGES * STAGE_BYTES)   // 110592 > C staging (128*132*4=67584)

// ---------------- device-global scratch ----------------
__device__ __align__(128) __nv_bfloat16 g_Wb[(size_t)V_PAD * D_DIM];
__device__ __align__(128) __nv_bfloat16 g_Ab[(size_t)TOKENS_MAX * D_DIM];
__device__ int   g_valid_idx[TOKENS_MAX];
__device__ int   g_tgt[TOKENS_MAX];
__device__ int   g_nvalid;
__device__ float g_sumexp[TOKENS_MAX];
__device__ float g_sumlogit[TOKENS_MAX];
__device__ float g_tlogit[TOKENS_MAX];

__device__ __forceinline__ uint32_t smem_u32(const void* p) {
    uint32_t a;
    asm("{ .reg .u64 t; cvta.to.shared.u64 t, %1; cvt.u32.u64 %0, t; }" : "=r"(a) : "l"(p));
    return a;
}
__device__ __forceinline__ void cp16(uint32_t dst, const void* src) {
    asm volatile("cp.async.cg.shared.global [%0], [%1], 16;\n" :: "r"(dst), "l"(src));
}

// ---------------- kernel 1: mask-dtype detect + compact valid tokens ----------------
__global__ void gather_kernel(const int* __restrict__ targets,
                              const unsigned char* __restrict__ masks_raw,
                              int n_tokens) {
    __shared__ int s_isu8;
    __shared__ int wsum[32];
    int tid = threadIdx.x;
    if (tid == 0) s_isu8 = 0;
    __syncthreads();

    int flag = 0;
    for (int i = tid; i < n_tokens; i += blockDim.x)
        if ((i & 3) != 0 && masks_raw[i] != 0) flag = 1;
    if (flag) atomicOr(&s_isu8, 1);
    __syncthreads();
    const bool isu8 = (s_isu8 != 0);
    const int* masks_i32 = (const int*)masks_raw;

    int C = (n_tokens + blockDim.x - 1) / blockDim.x;
    int start = tid * C;
    int end = min(start + C, n_tokens);
    int cnt = 0;
    for (int i = start; i < end; i++)
        cnt += isu8 ? (masks_raw[i] != 0) : (masks_i32[i] != 0);

    int lane = tid & 31, wid = tid >> 5;
    int v = cnt;
    #pragma unroll
    for (int o = 1; o < 32; o <<= 1) {
        int t = __shfl_up_sync(0xffffffffu, v, o);
        if (lane >= o) v += t;
    }
    if (lane == 31) wsum[wid] = v;
    __syncthreads();
    if (wid == 0) {
        int nw = blockDim.x >> 5;
        int w = (lane < nw) ? wsum[lane] : 0;
        #pragma unroll
        for (int o = 1; o < 32; o <<= 1) {
            int t = __shfl_up_sync(0xffffffffu, w, o);
            if (lane >= o) w += t;
        }
        wsum[lane] = w;
    }
    __syncthreads();
    int excl = v - cnt + (wid > 0 ? wsum[wid - 1] : 0);

    int off = excl;
    for (int i = start; i < end; i++) {
        bool mk = isu8 ? (masks_raw[i] != 0) : (masks_i32[i] != 0);
        if (mk) {
            g_valid_idx[off] = i;
            g_tgt[off] = targets[i];
            off++;
        }
    }
    if (tid == blockDim.x - 1) g_nvalid = excl + cnt;
}

// ---------------- kernel 2: gather + convert activations to bf16 ----------------
__global__ void build_a_kernel(const float* __restrict__ outputs) {
    int m = blockIdx.x;
    int tid = threadIdx.x;
    if (tid == 0) {
        g_sumexp[m] = 0.f;
        g_sumlogit[m] = 0.f;
        g_tlogit[m] = 0.f;
    }
    int nv = g_nvalid;
    __nv_bfloat16* dst = g_Ab + (size_t)m * D_DIM;
    if (m < nv) {
        const float* src = outputs + (size_t)g_valid_idx[m] * D_DIM;
        for (int i = tid * 4; i < D_DIM; i += blockDim.x * 4) {
            float4 v = *(const float4*)(src + i);
            *(__nv_bfloat162*)(dst + i)     = __floats2bfloat162_rn(v.x, v.y);
            *(__nv_bfloat162*)(dst + i + 2) = __floats2bfloat162_rn(v.z, v.w);
        }
    } else {
        __nv_bfloat162 z = __floats2bfloat162_rn(0.f, 0.f);
        for (int i = tid * 4; i < D_DIM; i += blockDim.x * 4) {
            *(__nv_bfloat162*)(dst + i)     = z;
            *(__nv_bfloat162*)(dst + i + 2) = z;
        }
    }
}

// ---------------- kernel 3: W fp32 -> bf16 (zero-pad to V_PAD) ----------------
__global__ void conv_w_kernel(const float* __restrict__ W) {
    long i = ((long)blockIdx.x * blockDim.x + threadIdx.x) * 4;
    const long nreal = (long)V_DIM * D_DIM;
    const long ntot  = (long)V_PAD * D_DIM;
    if (i < ntot) {
        if (i < nreal) {
            float4 v = *(const float4*)(W + i);
            *(__nv_bfloat162*)(g_Wb + i)     = __floats2bfloat162_rn(v.x, v.y);
            *(__nv_bfloat162*)(g_Wb + i + 2) = __floats2bfloat162_rn(v.z, v.w);
        } else {
            __nv_bfloat162 z = __floats2bfloat162_rn(0.f, 0.f);
            *(__nv_bfloat162*)(g_Wb + i)     = z;
            *(__nv_bfloat162*)(g_Wb + i + 2) = z;
        }
    }
}

// ---------------- kernel 4: 128x128x64 HMMA, warp tile 64x64, 2 CTAs/SM ----------------
__global__ void __launch_bounds__(128, 2) gemm_epilogue_kernel() {
    extern __shared__ char smem[];
    uint32_t sb = smem_u32(smem);

    int nv = g_nvalid;
    int m0 = blockIdx.x * BM;
    if (m0 >= nv) return;
    int n0 = blockIdx.y * BN;

    int tid = threadIdx.x;
    int warp = tid >> 5, lane = tid & 31;
    int wm = warp & 1;        // rows wm*64..+63
    int wn = warp >> 1;       // cols wn*64..+63

    // per-thread cp.async slots: 8 A chunks + 8 B chunks per stage (16B chunks)
    // stage row = 64 elems = 128B = 8 chunks; 128 rows => 1024 chunks per matrix
    uint32_t adst[8];
    size_t   asrc[8], bsrc[8];
    const char* Ag = (const char*)g_Ab;
    const char* Wg = (const char*)g_Wb;
    #pragma unroll
    for (int i = 0; i < 8; i++) {
        int c = tid + i * 128;
        int row = c >> 3, cc = (c & 7) << 4;
        adst[i] = (uint32_t)(row * (LDS_PAD * 2) + cc);
        asrc[i] = (size_t)(m0 + row) * 2048 + cc;
        bsrc[i] = (size_t)(n0 + row) * 2048 + cc;
    }

    wmma::fragment<wmma::accumulator, 16, 16, 16, float> acc[4][4];
    #pragma unroll
    for (int i = 0; i < 4; i++)
        #pragma unroll
        for (int j = 0; j < 4; j++)
            wmma::fill_fragment(acc[i][j], 0.0f);

    // prologue: 2 stages in flight
    #pragma unroll
    for (int s = 0; s < 2; s++) {
        uint32_t ab = sb + s * STAGE_BYTES;
        uint32_t bb = ab + A_STAGE_BYTES;
        size_t kb = (size_t)s * (BK * 2);
        #pragma unroll
        for (int i = 0; i < 8; i++) {
            cp16(ab + adst[i], Ag + asrc[i] + kb);
            cp16(bb + adst[i], Wg + bsrc[i] + kb);
        }
        asm volatile("cp.async.commit_group;" ::: "memory");
    }

    for (int j = 0; j < KSTEPS; j++) {
        asm volatile("cp.async.wait_group 1;" ::: "memory");
        __syncthreads();   // single barrier per K-step (16 total)

        // prefetch stage j+2 into slot (j+2)%3 == (j-1)%3, consumed before this barrier
        if (j + 2 < KSTEPS) {
            int s = (j + 2) % STAGES;
            uint32_t ab = sb + s * STAGE_BYTES;
            uint32_t bb = ab + A_STAGE_BYTES;
            size_t kb = (size_t)(j + 2) * (BK * 2);
            #pragma unroll
            for (int i = 0; i < 8; i++) {
                cp16(ab + adst[i], Ag + asrc[i] + kb);
                cp16(bb + adst[i], Wg + bsrc[i] + kb);
            }
        }
        asm volatile("cp.async.commit_group;" ::: "memory");

        // compute stage j: warp tile 64x64, 4 kk half-steps
        int s = j % STAGES;
        const __nv_bfloat16* As = (const __nv_bfloat16*)(smem + s * STAGE_BYTES);
        const __nv_bfloat16* Bs = (const __nv_bfloat16*)(smem + s * STAGE_BYTES + A_STAGE_BYTES);
        #pragma unroll
        for (int kk = 0; kk < BK; kk += 16) {
            wmma::fragment<wmma::matrix_a, 16, 16, 16, __nv_bfloat16, wmma::row_major> a[4];
            wmma::fragment<wmma::matrix_b, 16, 16, 16, __nv_bfloat16, wmma::col_major> b[4];
            #pragma unroll
            for (int i = 0; i < 4; i++)
                wmma::load_matrix_sync(a[i], As + (wm * 64 + i * 16) * LDS_PAD + kk, LDS_PAD);
            #pragma unroll
            for (int jj = 0; jj < 4; jj++)
                wmma::load_matrix_sync(b[jj], Bs + (wn * 64 + jj * 16) * LDS_PAD + kk, LDS_PAD);
            #pragma unroll
            for (int i = 0; i < 4; i++)
                #pragma unroll
                for (int jj = 0; jj < 4; jj++)
                    wmma::mma_sync(acc[i][jj], a[i], b[jj], acc[i][jj]);
        }
    }
    __syncthreads();   // protect smem reuse for C staging

    // ---- epilogue: stage C tile (fp32) in smem, reduce per row ----
    float* Cs = (float*)smem;
    #pragma unroll
    for (int i = 0; i < 4; i++)
        #pragma unroll
        for (int jj = 0; jj < 4; jj++)
            wmma::store_matrix_sync(Cs + (wm * 64 + i * 16) * CS_LD + wn * 64 + jj * 16,
                                    acc[i][jj], CS_LD, wmma::mem_row_major);
    __syncthreads();

    // one thread per row; column rotation (lane+k)&127 -> bank (5*lane+k)%32, conflict-free
    int row = tid;
    int gm = m0 + row;
    const float* crow = Cs + row * CS_LD;
    float se = 0.f, sl = 0.f;
    #pragma unroll 8
    for (int k = 0; k < 128; k++) {
        int c = (lane + k) & 127;
        int col = n0 + c;
        if (col < V_DIM) {
            float v = crow[c];
            se += __expf(v);
            sl += v;
        }
    }
    if (gm < nv) {
        atomicAdd(&g_sumexp[gm], se);
        atomicAdd(&g_sumlogit[gm], sl);
        int t = g_tgt[gm];
        if (t >= n0 && t < n0 + BN)
            g_tlogit[gm] = crow[t - n0];
    }
}

// ---------------- kernel 5: final scalar reduction ----------------
__global__ void final_kernel(float* __restrict__ out) {
    __shared__ double s_n[32], s_s[32];
    int tid = threadIdx.x;
    int nv = g_nvalid;
    double nll = 0.0, slp = 0.0;
    for (int m = tid; m < nv; m += blockDim.x) {
        float lse = logf(g_sumexp[m]);
        nll += (double)lse - (double)g_tlogit[m];
        slp += (double)g_sumlogit[m] - (double)V_DIM * (double)lse;
    }
    #pragma unroll
    for (int o = 16; o; o >>= 1) {
        nll += __shfl_down_sync(0xffffffffu, nll, o);
        slp += __shfl_down_sync(0xffffffffu, slp, o);
    }
    if ((tid & 31) == 0) { s_n[tid >> 5] = nll; s_s[tid >> 5] = slp; }
    __syncthreads();
    if (tid < 32) {
        int nw = blockDim.x >> 5;
        nll = (tid < nw) ? s_n[tid] : 0.0;
        slp = (tid < nw) ? s_s[tid] : 0.0;
        #pragma unroll
        for (int o = 16; o; o >>= 1) {
            nll += __shfl_down_sync(0xffffffffu, nll, o);
            slp += __shfl_down_sync(0xffffffffu, slp, o);
        }
        if (tid == 0) {
            double n = (double)nv;
            double loss = 0.9 * (nll / n) - 0.1 * (slp / (n * (double)V_DIM));
            out[0] = (float)loss;
        }
    }
}

// ---------------- launch ----------------
extern "C" void kernel_launch(void* const* d_in, const int* in_sizes, int n_in,
                              void* d_out, int out_size) {
    const int*           targets = (const int*)d_in[0];
    const unsigned char* masks   = (const unsigned char*)d_in[1];
    const float*         outputs = (const float*)d_in[2];
    const float*         W       = (const float*)d_in[3];
    int n_tokens = in_sizes[0];   // 4096

    static int s_attr_done = 0;
    if (!s_attr_done) {
        cudaFuncSetAttribute(gemm_epilogue_kernel,
                             cudaFuncAttributeMaxDynamicSharedMemorySize, SMEM_TOTAL);
        s_attr_done = 1;
    }

    gather_kernel<<<1, 1024>>>(targets, masks, n_tokens);
    build_a_kernel<<<n_tokens, 256>>>(outputs);

    long ntot = (long)V_PAD * D_DIM;
    int conv_blocks = (int)((ntot / 4 + 255) / 256);
    conv_w_kernel<<<conv_blocks, 256>>>(W);

    dim3 grid((TOKENS_MAX + BM - 1) / BM, N_TILES);
    gemm_epilogue_kernel<<<grid, 128, SMEM_TOTAL>>>();

    final_kernel<<<1, 1024>>>((float*)d_out);
}